// round 6
// baseline (speedup 1.0000x reference)
#include <cuda_runtime.h>
#include <cstdint>

// out[b,c,h,w] = x[b,c,2h,2w] * 0.5f     (Haar DWT subband sum collapses to this)
// x:  [16, 64, 512, 512] fp32,  out: [16, 64, 256, 256] fp32
//
// Warp-coalesced geometry (same as R4):
//   pair index p in [0, 33'554'432):  out float2 index = p
//   pair  = p & 127          (128 float2 per output row)
//   orow  = (p >> 7) & 255
//   bc    = p >> 15
//   input float4 index = bc*65536 + orow*256 + pair   (even row 2*orow)
//
// MLP=4: each block owns 1024 consecutive pairs; thread t processes
// pairs base+t+{0,256,512,768}. Every LDG.128 is 512B-contiguous per warp,
// every STG.64 coalesced. All four loads front-batched.

__device__ __forceinline__ long long pair_to_in_idx(unsigned p)
{
    unsigned pair = p & 127u;
    unsigned orow = (p >> 7) & 255u;
    unsigned bc   = p >> 15;
    return ((long long)bc << 16) + ((long long)orow << 8) + pair;
}

__global__ __launch_bounds__(256) void haar_sum_kernel(
    const float4* __restrict__ x, float2* __restrict__ out)
{
    unsigned i0 = blockIdx.x * 1024u + threadIdx.x;
    unsigned i1 = i0 + 256u;
    unsigned i2 = i0 + 512u;
    unsigned i3 = i0 + 768u;

    long long a0 = pair_to_in_idx(i0);
    long long a1 = pair_to_in_idx(i1);
    long long a2 = pair_to_in_idx(i2);
    long long a3 = pair_to_in_idx(i3);

    // four independent streaming loads in flight
    float4 v0 = __ldcs(&x[a0]);
    float4 v1 = __ldcs(&x[a1]);
    float4 v2 = __ldcs(&x[a2]);
    float4 v3 = __ldcs(&x[a3]);

    float2 o0, o1, o2, o3;
    o0.x = v0.x * 0.5f;  o0.y = v0.z * 0.5f;
    o1.x = v1.x * 0.5f;  o1.y = v1.z * 0.5f;
    o2.x = v2.x * 0.5f;  o2.y = v2.z * 0.5f;
    o3.x = v3.x * 0.5f;  o3.y = v3.z * 0.5f;

    __stcs(&out[i0], o0);
    __stcs(&out[i1], o1);
    __stcs(&out[i2], o2);
    __stcs(&out[i3], o3);
}

extern "C" void kernel_launch(void* const* d_in, const int* in_sizes, int n_in,
                              void* d_out, int out_size)
{
    const float4* x = (const float4*)d_in[0];
    float2* out     = (float2*)d_out;

    // out_size = 67,108,864 floats -> 33,554,432 pairs -> 1024 pairs per block
    long long n_pairs = (long long)out_size / 2;
    long long blocks  = n_pairs / 1024;                // 32768

    haar_sum_kernel<<<(unsigned)blocks, 256>>>(x, out);
}